// round 10
// baseline (speedup 1.0000x reference)
#include <cuda_runtime.h>
#include <cstdint>

#define FM 0xffffffffu
#define NW 32
#define INFV 1000000000.0f
#define KMASK 0xFFFFFFE0u   // key: high 27 bits value, low 5 bits lane

struct Feat {
    float cx, cy, area, sr, ar, bx, by, prob;
};

__device__ __forceinline__ Feat wall_features(const float* __restrict__ q) {
    float sx = q[0], sy = q[1], ex = q[2], ey = q[3], w = q[4], prob = q[5];
    float dx = ex - sx, dy = ey - sy;
    float len = sqrtf(dx * dx + dy * dy);
    float cx = (sx + ex) * 0.5f, cy = (sy + ey) * 0.5f;
    float area = len * w;
    float smaller = fminf(w, len), bigger = fmaxf(w, len);
    float sr = (bigger > 0.0f) ? (smaller / bigger) : 0.0f;
    float px, py;
    if (len > 0.0f) {
        float s = w * 0.5f / len;
        px = dy * s;
        py = -dx * s;
    } else {
        px = 0.0f;
        py = 0.0f;
    }
    float right = fmaxf(fmaxf(sx + px, sx - px), fmaxf(ex + px, ex - px));
    float top   = fmaxf(fmaxf(sy + py, sy - py), fmaxf(ey + py, ey - py));
    float bbw = fabsf((right - cx) * 2.0f);
    float bbh = fabsf((top  - cy) * 2.0f);
    float bba = bbw * bbh;
    float ar = (bba > 0.001f) ? (area / bba) : 1.0f;
    Feat f;
    f.cx = cx; f.cy = cy; f.area = area; f.sr = sr; f.ar = ar;
    f.bx = bbw; f.by = bbh; f.prob = prob;
    return f;
}

// Compute one cost-row term given broadcast row features.
__device__ __forceinline__ float pair_cost(
    float icx, float icy, float iarea, float isr, float iar,
    float ibx, float iby, float iprob, const Feat& fp) {
    float dcx = icx - fp.cx, dcy = icy - fp.cy;
    float center_d = dcx * dcx + dcy * dcy;
    float da = iarea - fp.area;
    float ds = isr   - fp.sr;
    float dr = iar   - fp.ar;
    float dh = ibx   - fp.bx;
    float dv = iby   - fp.by;
    float dp = iprob - fp.prob;
    float param_d = da * da + center_d + dr * dr + dh * dh + dv * dv + ds * ds;
    return 10.0f * (dp * dp) + param_d * iprob;
}

// One warp per TWO batches: the two independent JV solves are instruction-
// interleaved so each solve's redux/shfl chain stalls are filled by the other
// solve's work (per-warp ILP). Solve-level state is warp-uniform; inactive/
// finished solves run harmless padded steps with predicated commits.
__global__ void __launch_bounds__(32)
floorplanet_kernel(const float* __restrict__ params_true,
                   const float* __restrict__ params_pred,
                   float* __restrict__ out) {
    __shared__ float CA[NW * NW], CB[NW * NW];
    __shared__ int c4rA_sh[NW], c4rB_sh[NW];

    const int lane = threadIdx.x;
    const int bA = blockIdx.x * 2;
    const int bB = bA + 1;

    Feat ftA = wall_features(params_true + (size_t)bA * NW * 6 + lane * 6);
    Feat fpA = wall_features(params_pred + (size_t)bA * NW * 6 + lane * 6);
    Feat ftB = wall_features(params_true + (size_t)bB * NW * 6 + lane * 6);
    Feat fpB = wall_features(params_pred + (size_t)bB * NW * 6 + lane * 6);

    // Interleaved fill of CA/CB; track column mins.
    float cmA = INFV, cmB = INFV;
    int amA = 0, amB = 0;
#pragma unroll 4
    for (int i = 0; i < NW; i++) {
        float a0 = __shfl_sync(FM, ftA.cx,   i);
        float a1 = __shfl_sync(FM, ftA.cy,   i);
        float a2 = __shfl_sync(FM, ftA.area, i);
        float a3 = __shfl_sync(FM, ftA.sr,   i);
        float a4 = __shfl_sync(FM, ftA.ar,   i);
        float a5 = __shfl_sync(FM, ftA.bx,   i);
        float a6 = __shfl_sync(FM, ftA.by,   i);
        float a7 = __shfl_sync(FM, ftA.prob, i);
        float b0 = __shfl_sync(FM, ftB.cx,   i);
        float b1 = __shfl_sync(FM, ftB.cy,   i);
        float b2 = __shfl_sync(FM, ftB.area, i);
        float b3 = __shfl_sync(FM, ftB.sr,   i);
        float b4 = __shfl_sync(FM, ftB.ar,   i);
        float b5 = __shfl_sync(FM, ftB.bx,   i);
        float b6 = __shfl_sync(FM, ftB.by,   i);
        float b7 = __shfl_sync(FM, ftB.prob, i);

        float costA = pair_cost(a0, a1, a2, a3, a4, a5, a6, a7, fpA);
        float costB = pair_cost(b0, b1, b2, b3, b4, b5, b6, b7, fpB);
        CA[i * NW + lane] = costA;
        CB[i * NW + lane] = costB;
        if (costA < cmA) { cmA = costA; amA = i; }
        if (costB < cmB) { cmB = costB; amB = i; }
    }
    __syncwarp();

    // ---- Phase 1: column reduction (both solves, straight-line).
    float vA = cmA, uA = 0.0f, vB = cmB, uB = 0.0f;
    unsigned grpA = __match_any_sync(FM, amA);
    unsigned grpB = __match_any_sync(FM, amB);
    bool winA = ((__ffs(grpA) - 1) == lane);
    bool winB = ((__ffs(grpB) - 1) == lane);
    int row4colA = winA ? amA : -1;
    int row4colB = winB ? amB : -1;
    c4rA_sh[lane] = -1;
    c4rB_sh[lane] = -1;
    __syncwarp();
    if (winA) c4rA_sh[amA] = lane;
    if (winB) c4rB_sh[amB] = lane;
    __syncwarp();
    int col4rowA = c4rA_sh[lane];
    int col4rowB = c4rB_sh[lane];
    unsigned freerowsA = __ballot_sync(FM, col4rowA < 0);
    unsigned freerowsB = __ballot_sync(FM, col4rowB < 0);

    // ---- Phase 2': kick-free free-row pass, interleaved, branch-free pads.
    unsigned remA = freerowsA, remB = freerowsB;
    while (remA | remB) {
        bool aA = remA != 0, aB = remB != 0;
        int iA = aA ? (__ffs(remA) - 1) : 0;
        int iB = aB ? (__ffs(remB) - 1) : 0;
        remA &= remA - 1;
        remB &= remB - 1;
        float dA = fmaxf(CA[iA * NW + lane] - vA, 0.0f);
        float dB = fmaxf(CB[iB * NW + lane] - vB, 0.0f);
        unsigned kA = (__float_as_uint(dA) & KMASK) | (unsigned)lane;
        unsigned kB = (__float_as_uint(dB) & KMASK) | (unsigned)lane;
        unsigned mA = __reduce_min_sync(FM, kA);
        unsigned mB = __reduce_min_sync(FM, kB);
        int jA = mA & 31, jB = mB & 31;
        int rA = __shfl_sync(FM, row4colA, jA);
        int rB = __shfl_sync(FM, row4colB, jB);
        if (aA && lane == iA) uA = __uint_as_float(mA & KMASK);
        if (aB && lane == iB) uB = __uint_as_float(mB & KMASK);
        bool matA = aA && rA < 0;
        bool matB = aB && rB < 0;
        if (matA && lane == jA) row4colA = iA;
        if (matA && lane == iA) col4rowA = jA;
        if (matB && lane == jB) row4colB = iB;
        if (matB && lane == iB) col4rowB = jB;
        freerowsA &= matA ? ~(1u << iA) : FM;
        freerowsB &= matB ? ~(1u << iB) : FM;
    }

    // ---- Phase 3: SAP, biased slacks (slackb = slack + 1 > 0), interleaved.
    unsigned freecolsA = __ballot_sync(FM, row4colA < 0);
    unsigned freecolsB = __ballot_sync(FM, row4colB < 0);

    while (freerowsA | freerowsB) {
        bool aA = freerowsA != 0, aB = freerowsB != 0;
        int i0A = aA ? (__ffs(freerowsA) - 1) : 0;
        int i0B = aB ? (__ffs(freerowsB) - 1) : 0;
        freerowsA &= freerowsA - 1;
        freerowsB &= freerowsB - 1;

        float urA = __shfl_sync(FM, uA, row4colA & 31);
        float urB = __shfl_sync(FM, uB, row4colB & 31);
        float uiA = __shfl_sync(FM, uA, i0A);
        float uiB = __shfl_sync(FM, uB, i0B);
        unsigned SRA = 1u << i0A, SCA = 0u, mkeyA = 0xFFFFFFFFu;
        unsigned SRB = 1u << i0B, SCB = 0u, mkeyB = 0xFFFFFFFFu;
        unsigned laneorA = (unsigned)lane, laneorB = (unsigned)lane;
        float spcbA = INFV, spcbB = INFV;
        int pathA = -1, pathB = -1;
        float minValbA = 1.0f, minValbB = 1.0f;
        int irA = i0A, irB = i0B;
        float slackbA = (CA[i0A * NW + lane] - uiA - vA) + 1.0f;
        float slackbB = (CB[i0B * NW + lane] - uiB - vB) + 1.0f;
        bool doneA = !aA, doneB = !aB;
        int sinkA = 0, sinkB = 0;

        while (!(doneA && doneB)) {
            // --- solve A step (commits predicated on !doneA)
            unsigned skeyA = (__float_as_uint(slackbA) & KMASK) | laneorA;
            bool updA = !doneA && (skeyA < mkeyA);
            spcbA = updA ? __uint_as_float(skeyA & KMASK) : spcbA;
            pathA = updA ? irA : pathA;
            mkeyA = updA ? skeyA : mkeyA;
            unsigned omA = __reduce_min_sync(FM, mkeyA);
            // --- solve B step
            unsigned skeyB = (__float_as_uint(slackbB) & KMASK) | laneorB;
            bool updB = !doneB && (skeyB < mkeyB);
            spcbB = updB ? __uint_as_float(skeyB & KMASK) : spcbB;
            pathB = updB ? irB : pathB;
            mkeyB = updB ? skeyB : mkeyB;
            unsigned omB = __reduce_min_sync(FM, mkeyB);

            int jA = omA & 31;
            minValbA = doneA ? minValbA : __uint_as_float(omA & KMASK);
            SCA = doneA ? SCA : (SCA | (1u << jA));
            bool selA = !doneA && (lane == jA);
            laneorA = selA ? 0xFFFFFFFFu : laneorA;
            mkeyA = selA ? 0xFFFFFFFFu : mkeyA;
            bool nsA = !doneA && ((freecolsA >> jA) & 1u);
            int rA = __shfl_sync(FM, row4colA, jA);
            float urjA = __shfl_sync(FM, urA, jA);

            int jB = omB & 31;
            minValbB = doneB ? minValbB : __uint_as_float(omB & KMASK);
            SCB = doneB ? SCB : (SCB | (1u << jB));
            bool selB = !doneB && (lane == jB);
            laneorB = selB ? 0xFFFFFFFFu : laneorB;
            mkeyB = selB ? 0xFFFFFFFFu : mkeyB;
            bool nsB = !doneB && ((freecolsB >> jB) & 1u);
            int rB = __shfl_sync(FM, row4colB, jB);
            float urjB = __shfl_sync(FM, urB, jB);

            bool contA = !doneA && !nsA;
            SRA |= contA ? (1u << (rA & 31)) : 0u;
            irA = contA ? rA : irA;
            float nslA = CA[(rA & 31) * NW + lane] - ((urjA - minValbA) + vA);
            slackbA = contA ? nslA : slackbA;
            sinkA = nsA ? jA : sinkA;
            doneA = doneA || nsA;

            bool contB = !doneB && !nsB;
            SRB |= contB ? (1u << (rB & 31)) : 0u;
            irB = contB ? rB : irB;
            float nslB = CB[(rB & 31) * NW + lane] - ((urjB - minValbB) + vB);
            slackbB = contB ? nslB : slackbB;
            sinkB = nsB ? jB : sinkB;
            doneB = doneB || nsB;
        }

        // --- epilogue A (uniform branch)
        if (aA) {
            float spcb_c4r = __shfl_sync(FM, spcbA, col4rowA & 31);
            if ((SRA >> lane) & 1u)
                uA += (lane == i0A) ? (minValbA - 1.0f) : (minValbA - spcb_c4r);
            if ((SCA >> lane) & 1u) vA -= minValbA - spcbA;
            int j = sinkA;
            bool fin = false;
            while (!fin) {
                int pi = __shfl_sync(FM, pathA, j);
                if (lane == j) row4colA = pi;
                int jn = __shfl_sync(FM, col4rowA, pi);
                if (lane == pi) col4rowA = j;
                fin = (pi == i0A);
                j = jn;
            }
            freecolsA &= ~(1u << sinkA);
        }
        // --- epilogue B
        if (aB) {
            float spcb_c4r = __shfl_sync(FM, spcbB, col4rowB & 31);
            if ((SRB >> lane) & 1u)
                uB += (lane == i0B) ? (minValbB - 1.0f) : (minValbB - spcb_c4r);
            if ((SCB >> lane) & 1u) vB -= minValbB - spcbB;
            int j = sinkB;
            bool fin = false;
            while (!fin) {
                int pi = __shfl_sync(FM, pathB, j);
                if (lane == j) row4colB = pi;
                int jn = __shfl_sync(FM, col4rowB, pi);
                if (lane == pi) col4rowB = j;
                fin = (pi == i0B);
                j = jn;
            }
            freecolsB &= ~(1u << sinkB);
        }
    }

    // loss = sum_i C[i][col4row[i]] for both solves.
    float cA = CA[lane * NW + (col4rowA & 31)];
    float cB = CB[lane * NW + (col4rowB & 31)];
#pragma unroll
    for (int off = 16; off > 0; off >>= 1) {
        cA += __shfl_xor_sync(FM, cA, off);
        cB += __shfl_xor_sync(FM, cB, off);
    }
    if (lane == 0) {
        out[bA] = cA;
        out[bB] = cB;
    }
}

extern "C" void kernel_launch(void* const* d_in, const int* in_sizes, int n_in,
                              void* d_out, int out_size) {
    const float* params_true = (const float*)d_in[0];
    const float* params_pred = (const float*)d_in[1];
    float* out = (float*)d_out;
    (void)in_sizes; (void)n_in; (void)out_size;
    floorplanet_kernel<<<1024, 32>>>(params_true, params_pred, out);
}

// round 11
// speedup vs baseline: 1.4308x; 1.4308x over previous
#include <cuda_runtime.h>
#include <cstdint>

#define FM 0xffffffffu
#define NW 32
#define INFV 1000000000.0f
#define KMASK 0xFFFFFFE0u   // key: high 27 bits value, low 5 bits lane

struct Feat {
    float cx, cy, area, sr, ar, bx, by, prob;
};

__device__ __forceinline__ Feat wall_features(const float* __restrict__ q) {
    float sx = q[0], sy = q[1], ex = q[2], ey = q[3], w = q[4], prob = q[5];
    float dx = ex - sx, dy = ey - sy;
    float len = sqrtf(dx * dx + dy * dy);
    float cx = (sx + ex) * 0.5f, cy = (sy + ey) * 0.5f;
    float area = len * w;
    float smaller = fminf(w, len), bigger = fmaxf(w, len);
    float sr = (bigger > 0.0f) ? (smaller / bigger) : 0.0f;
    float px, py;
    if (len > 0.0f) {
        float s = w * 0.5f / len;
        px = dy * s;
        py = -dx * s;
    } else {
        px = 0.0f;
        py = 0.0f;
    }
    float right = fmaxf(fmaxf(sx + px, sx - px), fmaxf(ex + px, ex - px));
    float top   = fmaxf(fmaxf(sy + py, sy - py), fmaxf(ey + py, ey - py));
    float bbw = fabsf((right - cx) * 2.0f);
    float bbh = fabsf((top  - cy) * 2.0f);
    float bba = bbw * bbh;
    float ar = (bba > 0.001f) ? (area / bba) : 1.0f;
    Feat f;
    f.cx = cx; f.cy = cy; f.area = area; f.sr = sr; f.ar = ar;
    f.bx = bbw; f.by = bbh; f.prob = prob;
    return f;
}

// One warp per batch; columns (pred walls) <-> lanes.
// JV: column reduction + kick-free free-row pass + SAP.
// SAP: M[j][l] = C[row4col[j]][l] staging (refresh only during augmentation),
// predecessor-COLUMN path recording (no per-iteration row4col shfl), scanned-
// row set derived from col4row/SC in the epilogue (no SR maintenance).
__global__ void __launch_bounds__(32)
floorplanet_kernel(const float* __restrict__ params_true,
                   const float* __restrict__ params_pred,
                   float* __restrict__ out) {
    __shared__ float C[NW * NW];
    __shared__ float M[NW * NW];
    __shared__ float4 F0[NW], F1[NW];
    __shared__ int c4r_sh[NW];

    const int b = blockIdx.x;
    const int lane = threadIdx.x;

    Feat ft = wall_features(params_true + (size_t)b * NW * 6 + lane * 6);
    Feat fp = wall_features(params_pred + (size_t)b * NW * 6 + lane * 6);

    // Stage row (true-wall) features in shared: 2 x LDS.128 broadcast per row
    // replaces 8 shfls per row in the fill loop.
    F0[lane] = make_float4(ft.cx, ft.cy, ft.area, ft.sr);
    F1[lane] = make_float4(ft.ar, ft.bx, ft.by, ft.prob);
    __syncwarp();

    // Fill C[i][lane]; track column min on the fly.
    float cm = INFV;
    int am = 0;
#pragma unroll 4
    for (int i = 0; i < NW; i++) {
        float4 g0 = F0[i];
        float4 g1 = F1[i];
        float dcx = g0.x - fp.cx, dcy = g0.y - fp.cy;
        float center_d = dcx * dcx + dcy * dcy;
        float da = g0.z - fp.area;
        float ds = g0.w - fp.sr;
        float dr = g1.x - fp.ar;
        float dh = g1.y - fp.bx;
        float dv = g1.z - fp.by;
        float dp = g1.w - fp.prob;
        float param_d = da * da + center_d + dr * dr + dh * dh + dv * dv + ds * ds;
        float cost = 10.0f * (dp * dp) + param_d * g1.w;
        C[i * NW + lane] = cost;
        if (cost < cm) { cm = cost; am = i; }
    }
    __syncwarp();

    // ---- Phase 1: column reduction. v[j]=colmin, greedily match argmin rows.
    float v = cm, u = 0.0f;
    unsigned grp = __match_any_sync(FM, am);
    bool winner = ((__ffs(grp) - 1) == lane);
    int row4col = winner ? am : -1;
    c4r_sh[lane] = -1;
    __syncwarp();
    if (winner) c4r_sh[am] = lane;
    __syncwarp();
    int col4row = c4r_sh[lane];
    unsigned freerows = __ballot_sync(FM, col4row < 0);

    // ---- Phase 2': kick-free free-row pass. Each free row takes its argmin
    // column iff unmatched; else keeps feasible dual u[i] = min reduced cost
    // (rounded down -> reduced costs stay >= 0) and stays free for SAP.
    unsigned rem = freerows;
    while (rem) {
        const int i = __ffs(rem) - 1;
        rem &= rem - 1;
        float d = fmaxf(C[i * NW + lane] - v, 0.0f);
        unsigned k = (__float_as_uint(d) & KMASK) | (unsigned)lane;
        unsigned m = __reduce_min_sync(FM, k);
        int j = m & 31;
        int r = __shfl_sync(FM, row4col, j);
        float umin = __uint_as_float(m & KMASK);
        if (lane == i) u = umin;
        if (r < 0) {
            if (lane == j) row4col = i;
            if (lane == i) col4row = j;
            freerows &= ~(1u << i);
        }
    }

    // ---- Phase 3: SAP, biased slacks (slackb = slack + 1 > 0).
    unsigned freecols = __ballot_sync(FM, row4col < 0);
    if (freerows) {
        // Stage M[j][l] = C[row4col[j]][l] for matched columns (once).
        c4r_sh[lane] = row4col;
        __syncwarp();
#pragma unroll 1
        for (int j = 0; j < NW; j++) {
            int r = c4r_sh[j];
            if (r >= 0) M[j * NW + lane] = C[r * NW + lane];
        }
        __syncwarp();
    }

    while (freerows) {
        const int i0 = __ffs(freerows) - 1;
        freerows &= freerows - 1;

        float ur = __shfl_sync(FM, u, row4col & 31);  // u[row4col[lane]]
        float ui = __shfl_sync(FM, u, i0);
        unsigned SC = 0u;
        unsigned mkey = 0xFFFFFFFFu;
        unsigned laneor = (unsigned)lane;   // ~0 once lane enters SC
        float spcb = INFV;
        int pathcol = 32;                   // predecessor column (32 == i0)
        int srccol = 32;                    // column feeding current slackb
        float minValb = 1.0f;
        float slackb = (C[i0 * NW + lane] - ui - v) + 1.0f;   // >= 1
        int sink;

        for (;;) {
            unsigned skey = (__float_as_uint(slackb) & KMASK) | laneor;
            if (skey < mkey) {              // off-chain bookkeeping
                mkey = skey;
                spcb = __uint_as_float(skey & KMASK);
                pathcol = srccol;
            }
            unsigned om = __reduce_min_sync(FM, mkey);
            int j = om & 31;
            minValb = __uint_as_float(om & KMASK);
            SC |= 1u << j;
            if (lane == j) { laneor = 0xFFFFFFFFu; mkey = 0xFFFFFFFFu; }
            if ((freecols >> j) & 1u) { sink = j; break; }
            srccol = j;
            float urj = __shfl_sync(FM, ur, j);       // overlaps the M LDS
            slackb = M[j * NW + lane] - ((urj - minValb) + v);
        }

        // Dual updates. Scanned rows = {i0} U {rows matched to SC columns}.
        float spcb_c4r = __shfl_sync(FM, spcb, col4row & 31);
        bool inSR = (lane == i0) ||
                    ((col4row >= 0) && ((SC >> col4row) & 1u));
        if (inSR)
            u += (lane == i0) ? (minValb - 1.0f) : (minValb - spcb_c4r);
        if ((SC >> lane) & 1u) v -= minValb - spcb;

        // Augment along the predecessor-column chain; refresh M on the way.
        int j = sink;
        for (;;) {
            int pc = __shfl_sync(FM, pathcol, j);
            int rc = __shfl_sync(FM, row4col, pc & 31);   // old row of pc
            int pi = (pc == 32) ? i0 : rc;
            if (lane == j) row4col = pi;
            if (lane == pi) col4row = j;
            M[j * NW + lane] = C[pi * NW + lane];
            if (pc == 32) break;
            j = pc;
        }
        freecols &= ~(1u << sink);
    }

    // loss = sum_i C[i][col4row[i]]
    float c = C[lane * NW + (col4row & 31)];
#pragma unroll
    for (int off = 16; off > 0; off >>= 1)
        c += __shfl_xor_sync(FM, c, off);
    if (lane == 0) out[b] = c;
}

extern "C" void kernel_launch(void* const* d_in, const int* in_sizes, int n_in,
                              void* d_out, int out_size) {
    const float* params_true = (const float*)d_in[0];
    const float* params_pred = (const float*)d_in[1];
    float* out = (float*)d_out;
    (void)in_sizes; (void)n_in; (void)out_size;
    floorplanet_kernel<<<2048, 32>>>(params_true, params_pred, out);
}

// round 12
// speedup vs baseline: 1.4321x; 1.0010x over previous
#include <cuda_runtime.h>
#include <cstdint>

#define FM 0xffffffffu
#define NW 32
#define INFV 1000000000.0f
#define KMASK 0xFFFFFFE0u   // key: high 27 bits value, low 5 bits lane

struct Feat {
    float cx, cy, area, sr, ar, bx, by, prob;
};

__device__ __forceinline__ Feat wall_features(const float* __restrict__ q) {
    float sx = q[0], sy = q[1], ex = q[2], ey = q[3], w = q[4], prob = q[5];
    float dx = ex - sx, dy = ey - sy;
    float len = sqrtf(dx * dx + dy * dy);
    float cx = (sx + ex) * 0.5f, cy = (sy + ey) * 0.5f;
    float area = len * w;
    float smaller = fminf(w, len), bigger = fmaxf(w, len);
    float sr = (bigger > 0.0f) ? (smaller / bigger) : 0.0f;
    float px, py;
    if (len > 0.0f) {
        float s = w * 0.5f / len;
        px = dy * s;
        py = -dx * s;
    } else {
        px = 0.0f;
        py = 0.0f;
    }
    float right = fmaxf(fmaxf(sx + px, sx - px), fmaxf(ex + px, ex - px));
    float top   = fmaxf(fmaxf(sy + py, sy - py), fmaxf(ey + py, ey - py));
    float bbw = fabsf((right - cx) * 2.0f);
    float bbh = fabsf((top  - cy) * 2.0f);
    float bba = bbw * bbh;
    float ar = (bba > 0.001f) ? (area / bba) : 1.0f;
    Feat f;
    f.cx = cx; f.cy = cy; f.area = area; f.sr = sr; f.ar = ar;
    f.bx = bbw; f.by = bbh; f.prob = prob;
    return f;
}

// One warp per batch; columns (pred walls) <-> lanes.
// JV: column reduction + kick-free free-row pass + SAP.
// SAP: M[j][l] = C[row4col[j]][l] staging; predecessor-column path recording;
// SC derived from the laneor flag in the epilogue (no per-iteration SC/spcb
// maintenance: spcb is assigned once at selection, where it equals minValb).
__global__ void __launch_bounds__(32)
floorplanet_kernel(const float* __restrict__ params_true,
                   const float* __restrict__ params_pred,
                   float* __restrict__ out) {
    __shared__ float C[NW * NW];
    __shared__ float M[NW * NW];
    __shared__ float4 F0[NW], F1[NW];
    __shared__ int c4r_sh[NW];

    const int b = blockIdx.x;
    const int lane = threadIdx.x;

    Feat ft = wall_features(params_true + (size_t)b * NW * 6 + lane * 6);
    Feat fp = wall_features(params_pred + (size_t)b * NW * 6 + lane * 6);

    // Stage row (true-wall) features: 2 broadcast LDS.128 per row in the fill.
    F0[lane] = make_float4(ft.cx, ft.cy, ft.area, ft.sr);
    F1[lane] = make_float4(ft.ar, ft.bx, ft.by, ft.prob);
    __syncwarp();

    // Fill C[i][lane]; track column min on the fly.
    float cm = INFV;
    int am = 0;
#pragma unroll 4
    for (int i = 0; i < NW; i++) {
        float4 g0 = F0[i];
        float4 g1 = F1[i];
        float dcx = g0.x - fp.cx, dcy = g0.y - fp.cy;
        float center_d = dcx * dcx + dcy * dcy;
        float da = g0.z - fp.area;
        float ds = g0.w - fp.sr;
        float dr = g1.x - fp.ar;
        float dh = g1.y - fp.bx;
        float dv = g1.z - fp.by;
        float dp = g1.w - fp.prob;
        float param_d = da * da + center_d + dr * dr + dh * dh + dv * dv + ds * ds;
        float cost = 10.0f * (dp * dp) + param_d * g1.w;
        C[i * NW + lane] = cost;
        if (cost < cm) { cm = cost; am = i; }
    }
    __syncwarp();

    // ---- Phase 1: column reduction. v[j]=colmin, greedily match argmin rows.
    float v = cm, u = 0.0f;
    unsigned grp = __match_any_sync(FM, am);
    bool winner = ((__ffs(grp) - 1) == lane);
    int row4col = winner ? am : -1;
    c4r_sh[lane] = -1;
    __syncwarp();
    if (winner) c4r_sh[am] = lane;
    __syncwarp();
    int col4row = c4r_sh[lane];
    unsigned freerows = __ballot_sync(FM, col4row < 0);

    // ---- Phase 2': kick-free free-row pass. Each free row takes its argmin
    // column iff unmatched; else keeps feasible dual u[i] = min reduced cost
    // (rounded down -> reduced costs stay >= 0) and stays free for SAP.
    unsigned rem = freerows;
    while (rem) {
        const int i = __ffs(rem) - 1;
        rem &= rem - 1;
        float d = fmaxf(C[i * NW + lane] - v, 0.0f);
        unsigned k = (__float_as_uint(d) & KMASK) | (unsigned)lane;
        unsigned m = __reduce_min_sync(FM, k);
        int j = m & 31;
        int r = __shfl_sync(FM, row4col, j);
        float umin = __uint_as_float(m & KMASK);
        if (lane == i) u = umin;
        if (r < 0) {
            if (lane == j) row4col = i;
            if (lane == i) col4row = j;
            freerows &= ~(1u << i);
        }
    }

    // ---- Phase 3: SAP, biased slacks (slackb = slack + 1 > 0).
    unsigned freecols = __ballot_sync(FM, row4col < 0);
    if (freerows) {
        // Stage M[j][l] = C[row4col[j]][l] for matched columns (once).
        c4r_sh[lane] = row4col;
        __syncwarp();
#pragma unroll 1
        for (int j = 0; j < NW; j++) {
            int r = c4r_sh[j];
            if (r >= 0) M[j * NW + lane] = C[r * NW + lane];
        }
        __syncwarp();
    }

    while (freerows) {
        const int i0 = __ffs(freerows) - 1;
        freerows &= freerows - 1;

        float ur = __shfl_sync(FM, u, row4col & 31);  // u[row4col[lane]]
        float ui = __shfl_sync(FM, u, i0);
        unsigned mkey = 0xFFFFFFFFu;
        unsigned laneor = (unsigned)lane;   // ~0 once lane is selected (SC)
        float spcb = INFV;                  // set once, at selection
        int pathcol = 32;                   // predecessor column (32 == i0)
        int j = 32;                         // previous selection (sentinel)
        float minValb = 1.0f;
        float slackb = (C[i0 * NW + lane] - ui - v) + 1.0f;   // >= 1
        int sink;

        for (;;) {
            unsigned skey = (__float_as_uint(slackb) & KMASK) | laneor;
            bool upd = skey < mkey;
            mkey = upd ? skey : mkey;
            pathcol = upd ? j : pathcol;
            unsigned om = __reduce_min_sync(FM, mkey);
            j = om & 31;
            minValb = __uint_as_float(om & KMASK);
            if (lane == j) {                // selection: freeze spcb, retire key
                spcb = minValb;
                laneor = 0xFFFFFFFFu;
                mkey = 0xFFFFFFFFu;
            }
            if ((freecols >> j) & 1u) { sink = j; break; }
            float urj = __shfl_sync(FM, ur, j);       // overlaps the M LDS
            slackb = M[j * NW + lane] - ((urj - minValb) + v);
        }

        // Dual updates. SC = selected lanes; scanned rows = {i0} U matched(SC).
        unsigned SC = __ballot_sync(FM, laneor == 0xFFFFFFFFu);
        float spcb_c4r = __shfl_sync(FM, spcb, col4row & 31);
        bool inSR = (lane == i0) ||
                    ((col4row >= 0) && ((SC >> col4row) & 1u));
        if (inSR)
            u += (lane == i0) ? (minValb - 1.0f) : (minValb - spcb_c4r);
        if ((SC >> lane) & 1u) v -= minValb - spcb;

        // Augment along the predecessor-column chain; refresh M on the way.
        int jj = sink;
        for (;;) {
            int pc = __shfl_sync(FM, pathcol, jj);
            int rc = __shfl_sync(FM, row4col, pc & 31);   // old row of pc
            int pi = (pc == 32) ? i0 : rc;
            if (lane == jj) row4col = pi;
            if (lane == pi) col4row = jj;
            M[jj * NW + lane] = C[pi * NW + lane];
            if (pc == 32) break;
            jj = pc;
        }
        freecols &= ~(1u << sink);
    }

    // loss = sum_i C[i][col4row[i]]
    float c = C[lane * NW + (col4row & 31)];
#pragma unroll
    for (int off = 16; off > 0; off >>= 1)
        c += __shfl_xor_sync(FM, c, off);
    if (lane == 0) out[b] = c;
}

extern "C" void kernel_launch(void* const* d_in, const int* in_sizes, int n_in,
                              void* d_out, int out_size) {
    const float* params_true = (const float*)d_in[0];
    const float* params_pred = (const float*)d_in[1];
    float* out = (float*)d_out;
    (void)in_sizes; (void)n_in; (void)out_size;
    floorplanet_kernel<<<2048, 32>>>(params_true, params_pred, out);
}

// round 13
// speedup vs baseline: 1.4419x; 1.0068x over previous
#include <cuda_runtime.h>
#include <cstdint>

#define FM 0xffffffffu
#define NW 32
#define INFV 1000000000.0f
#define KMASK 0xFFFFFFE0u   // key: high 27 bits value, low 5 bits lane

// packed f32x2 helpers (sm_103a dual-fp32 pipe)
#define PK2(dst, lo, hi) \
    asm("mov.b64 %0, {%1, %2};" : "=l"(dst) : "f"(lo), "f"(hi))
#define UPK2(lo, hi, src) \
    asm("mov.b64 {%0, %1}, %2;" : "=f"(lo), "=f"(hi) : "l"(src))
#define ADD2(d, a, b) \
    asm("add.rn.f32x2 %0, %1, %2;" : "=l"(d) : "l"(a), "l"(b))
#define MUL2(d, a, b) \
    asm("mul.rn.f32x2 %0, %1, %2;" : "=l"(d) : "l"(a), "l"(b))
#define FMA2(d, a, b, c) \
    asm("fma.rn.f32x2 %0, %1, %2, %3;" : "=l"(d) : "l"(a), "l"(b), "l"(c))

struct Feat {
    float cx, cy, area, sr, ar, bx, by, prob;
};

__device__ __forceinline__ Feat wall_features(const float* __restrict__ q) {
    float sx = q[0], sy = q[1], ex = q[2], ey = q[3], w = q[4], prob = q[5];
    float dx = ex - sx, dy = ey - sy;
    float len = sqrtf(dx * dx + dy * dy);
    float cx = (sx + ex) * 0.5f, cy = (sy + ey) * 0.5f;
    float area = len * w;
    float smaller = fminf(w, len), bigger = fmaxf(w, len);
    float sr = (bigger > 0.0f) ? (smaller / bigger) : 0.0f;
    float px, py;
    if (len > 0.0f) {
        float s = w * 0.5f / len;
        px = dy * s;
        py = -dx * s;
    } else {
        px = 0.0f;
        py = 0.0f;
    }
    float right = fmaxf(fmaxf(sx + px, sx - px), fmaxf(ex + px, ex - px));
    float top   = fmaxf(fmaxf(sy + py, sy - py), fmaxf(ey + py, ey - py));
    float bbw = fabsf((right - cx) * 2.0f);
    float bbh = fabsf((top  - cy) * 2.0f);
    float bba = bbw * bbh;
    float ar = (bba > 0.001f) ? (area / bba) : 1.0f;
    Feat f;
    f.cx = cx; f.cy = cy; f.area = area; f.sr = sr; f.ar = ar;
    f.bx = bbw; f.by = bbh; f.prob = prob;
    return f;
}

// One warp per batch; columns (pred walls) <-> lanes.
// Fill: f32x2-packed, two rows per iteration (pair-interleaved feature
// staging so LDS.128 yields ready-packed operands). JV: column reduction +
// kick-free free-row pass + SAP with M staging & predecessor-column paths.
__global__ void __launch_bounds__(32)
floorplanet_kernel(const float* __restrict__ params_true,
                   const float* __restrict__ params_pred,
                   float* __restrict__ out) {
    __shared__ float C[NW * NW];
    __shared__ float M[NW * NW];
    __shared__ float G[16 * 16];   // G[pair*16 + feat*2 + half]
    __shared__ int c4r_sh[NW];

    const int b = blockIdx.x;
    const int lane = threadIdx.x;

    Feat ft = wall_features(params_true + (size_t)b * NW * 6 + lane * 6);
    Feat fp = wall_features(params_pred + (size_t)b * NW * 6 + lane * 6);

    // Stage row features pair-interleaved: pair ip = lane>>1, half = lane&1.
    {
        float* g = G + (lane >> 1) * 16 + (lane & 1);
        g[0]  = ft.cx;   g[2]  = ft.cy;
        g[4]  = ft.area; g[6]  = ft.sr;
        g[8]  = ft.ar;   g[10] = ft.bx;
        g[12] = ft.by;   g[14] = ft.prob;
    }
    // Per-lane packed constants: negated pred features (sub == add of neg).
    uint64_t nx2, ny2, na2, ns2, nr2, nbx2, nby2, np2, ten2;
    PK2(nx2,  -fp.cx,   -fp.cx);
    PK2(ny2,  -fp.cy,   -fp.cy);
    PK2(na2,  -fp.area, -fp.area);
    PK2(ns2,  -fp.sr,   -fp.sr);
    PK2(nr2,  -fp.ar,   -fp.ar);
    PK2(nbx2, -fp.bx,   -fp.bx);
    PK2(nby2, -fp.by,   -fp.by);
    PK2(np2,  -fp.prob, -fp.prob);
    PK2(ten2, 10.0f, 10.0f);
    __syncwarp();

    // Fill C two rows at a time; track column min on the fly.
    float cm = INFV;
    int am = 0;
#pragma unroll 4
    for (int ip = 0; ip < 16; ip++) {
        const uint64_t* g = (const uint64_t*)(G + ip * 16);
        uint64_t x2 = g[0], y2 = g[1], a2 = g[2], s2 = g[3];
        uint64_t r2 = g[4], bx2 = g[5], by2 = g[6], p2 = g[7];

        uint64_t d0, d1, d2, d3, d4, d5, d6, dp, pd, t, cost2;
        ADD2(d0, x2,  nx2);
        ADD2(d1, y2,  ny2);
        ADD2(d2, a2,  na2);
        ADD2(d3, s2,  ns2);
        ADD2(d4, r2,  nr2);
        ADD2(d5, bx2, nbx2);
        ADD2(d6, by2, nby2);
        ADD2(dp, p2,  np2);
        MUL2(pd, d0, d0);
        FMA2(pd, d1, d1, pd);
        FMA2(pd, d2, d2, pd);
        FMA2(pd, d3, d3, pd);
        FMA2(pd, d4, d4, pd);
        FMA2(pd, d5, d5, pd);
        FMA2(pd, d6, d6, pd);
        MUL2(t, dp, dp);
        MUL2(t, t, ten2);
        FMA2(cost2, pd, p2, t);      // 10*dp^2 + param_d * iprob

        float c0, c1;
        UPK2(c0, c1, cost2);
        C[(2 * ip) * NW + lane] = c0;
        C[(2 * ip + 1) * NW + lane] = c1;
        if (c0 < cm) { cm = c0; am = 2 * ip; }
        if (c1 < cm) { cm = c1; am = 2 * ip + 1; }
    }
    __syncwarp();

    // ---- Phase 1: column reduction. v[j]=colmin, greedily match argmin rows.
    float v = cm, u = 0.0f;
    unsigned grp = __match_any_sync(FM, am);
    bool winner = ((__ffs(grp) - 1) == lane);
    int row4col = winner ? am : -1;
    c4r_sh[lane] = -1;
    __syncwarp();
    if (winner) c4r_sh[am] = lane;
    __syncwarp();
    int col4row = c4r_sh[lane];
    unsigned freerows = __ballot_sync(FM, col4row < 0);

    // ---- Phase 2': kick-free free-row pass. d = C - colmin >= 0 exactly.
    unsigned rem = freerows;
    while (rem) {
        const int i = __ffs(rem) - 1;
        rem &= rem - 1;
        float d = C[i * NW + lane] - v;
        unsigned k = (__float_as_uint(d) & KMASK) | (unsigned)lane;
        unsigned m = __reduce_min_sync(FM, k);
        int j = m & 31;
        int r = __shfl_sync(FM, row4col, j);
        float umin = __uint_as_float(m & KMASK);
        if (lane == i) u = umin;
        if (r < 0) {
            if (lane == j) row4col = i;
            if (lane == i) col4row = j;
            freerows &= ~(1u << i);
        }
    }

    // ---- Phase 3: SAP, biased slacks (slackb = slack + 1 > 0).
    unsigned freecols = __ballot_sync(FM, row4col < 0);
    if (freerows) {
        // Branchless M staging: free columns get a dummy row (never read
        // before being overwritten during augmentation).
        c4r_sh[lane] = row4col;
        __syncwarp();
#pragma unroll 1
        for (int j = 0; j < NW; j++) {
            int r = c4r_sh[j];
            M[j * NW + lane] = C[(r & 31) * NW + lane];
        }
        __syncwarp();
    }

    while (freerows) {
        const int i0 = __ffs(freerows) - 1;
        freerows &= freerows - 1;

        float ur = __shfl_sync(FM, u, row4col & 31);  // u[row4col[lane]]
        float ui = __shfl_sync(FM, u, i0);
        unsigned mkey = 0xFFFFFFFFu;
        unsigned laneor = (unsigned)lane;   // ~0 once lane is selected (SC)
        float spcb = INFV;                  // set once, at selection
        int pathcol = 32;                   // predecessor column (32 == i0)
        int j = 32;                         // previous selection (sentinel)
        float minValb = 1.0f;
        float slackb = (C[i0 * NW + lane] - ui - v) + 1.0f;   // >= 1
        int sink;

        for (;;) {
            unsigned skey = (__float_as_uint(slackb) & KMASK) | laneor;
            bool upd = skey < mkey;
            mkey = upd ? skey : mkey;
            pathcol = upd ? j : pathcol;
            unsigned om = __reduce_min_sync(FM, mkey);
            j = om & 31;
            minValb = __uint_as_float(om & KMASK);
            if (lane == j) {                // selection: freeze spcb, retire key
                spcb = minValb;
                laneor = 0xFFFFFFFFu;
                mkey = 0xFFFFFFFFu;
            }
            if ((freecols >> j) & 1u) { sink = j; break; }
            float urj = __shfl_sync(FM, ur, j);       // overlaps the M LDS
            slackb = M[j * NW + lane] - ((urj - minValb) + v);
        }

        // Dual updates. SC = selected lanes; scanned rows = {i0} U matched(SC).
        unsigned SC = __ballot_sync(FM, laneor == 0xFFFFFFFFu);
        float spcb_c4r = __shfl_sync(FM, spcb, col4row & 31);
        bool inSR = (lane == i0) ||
                    ((col4row >= 0) && ((SC >> col4row) & 1u));
        if (inSR)
            u += (lane == i0) ? (minValb - 1.0f) : (minValb - spcb_c4r);
        if ((SC >> lane) & 1u) v -= minValb - spcb;

        // Augment along the predecessor-column chain; refresh M on the way.
        int jj = sink;
        for (;;) {
            int pc = __shfl_sync(FM, pathcol, jj);
            int rc = __shfl_sync(FM, row4col, pc & 31);   // old row of pc
            int pi = (pc == 32) ? i0 : rc;
            if (lane == jj) row4col = pi;
            if (lane == pi) col4row = jj;
            M[jj * NW + lane] = C[pi * NW + lane];
            if (pc == 32) break;
            jj = pc;
        }
        freecols &= ~(1u << sink);
    }

    // loss = sum_i C[i][col4row[i]]
    float c = C[lane * NW + (col4row & 31)];
#pragma unroll
    for (int off = 16; off > 0; off >>= 1)
        c += __shfl_xor_sync(FM, c, off);
    if (lane == 0) out[b] = c;
}

extern "C" void kernel_launch(void* const* d_in, const int* in_sizes, int n_in,
                              void* d_out, int out_size) {
    const float* params_true = (const float*)d_in[0];
    const float* params_pred = (const float*)d_in[1];
    float* out = (float*)d_out;
    (void)in_sizes; (void)n_in; (void)out_size;
    floorplanet_kernel<<<2048, 32>>>(params_true, params_pred, out);
}

// round 14
// speedup vs baseline: 1.4660x; 1.0167x over previous
#include <cuda_runtime.h>
#include <cstdint>

#define FM 0xffffffffu
#define NW 32
#define INFV 1000000000.0f
#define KMASK6 0xFFFFFFC0u  // key: high 26 bits value, bit5 matched-flag, low 5 lane

// packed f32x2 helpers (sm_103a dual-fp32 pipe)
#define PK2(dst, lo, hi) \
    asm("mov.b64 %0, {%1, %2};" : "=l"(dst) : "f"(lo), "f"(hi))
#define UPK2(lo, hi, src) \
    asm("mov.b64 {%0, %1}, %2;" : "=f"(lo), "=f"(hi) : "l"(src))
#define ADD2(d, a, b) \
    asm("add.rn.f32x2 %0, %1, %2;" : "=l"(d) : "l"(a), "l"(b))
#define MUL2(d, a, b) \
    asm("mul.rn.f32x2 %0, %1, %2;" : "=l"(d) : "l"(a), "l"(b))
#define FMA2(d, a, b, c) \
    asm("fma.rn.f32x2 %0, %1, %2, %3;" : "=l"(d) : "l"(a), "l"(b), "l"(c))

struct Feat {
    float cx, cy, area, sr, ar, bx, by, prob;
};

__device__ __forceinline__ Feat wall_features(const float* __restrict__ q) {
    float sx = q[0], sy = q[1], ex = q[2], ey = q[3], w = q[4], prob = q[5];
    float dx = ex - sx, dy = ey - sy;
    float len = sqrtf(dx * dx + dy * dy);
    float cx = (sx + ex) * 0.5f, cy = (sy + ey) * 0.5f;
    float area = len * w;
    float smaller = fminf(w, len), bigger = fmaxf(w, len);
    float sr = (bigger > 0.0f) ? (smaller / bigger) : 0.0f;
    float px, py;
    if (len > 0.0f) {
        float s = w * 0.5f / len;
        px = dy * s;
        py = -dx * s;
    } else {
        px = 0.0f;
        py = 0.0f;
    }
    float right = fmaxf(fmaxf(sx + px, sx - px), fmaxf(ex + px, ex - px));
    float top   = fmaxf(fmaxf(sy + py, sy - py), fmaxf(ey + py, ey - py));
    float bbw = fabsf((right - cx) * 2.0f);
    float bbh = fabsf((top  - cy) * 2.0f);
    float bba = bbw * bbh;
    float ar = (bba > 0.001f) ? (area / bba) : 1.0f;
    Feat f;
    f.cx = cx; f.cy = cy; f.area = area; f.sr = sr; f.ar = ar;
    f.bx = bbw; f.by = bbh; f.prob = prob;
    return f;
}

// One warp per batch; columns (pred walls) <-> lanes.
// Keys carry (value:26 | matched:1 | lane:5): argmin reductions break value
// ties in favor of FREE columns, so phase-2' matches more rows and SAP
// phases terminate at the first free column among the minimal set; sink
// detection is bit 5 of the reduce result (no freecols bookkeeping).
__global__ void __launch_bounds__(32)
floorplanet_kernel(const float* __restrict__ params_true,
                   const float* __restrict__ params_pred,
                   float* __restrict__ out) {
    __shared__ float C[NW * NW];
    __shared__ float M[NW * NW];
    __shared__ float G[16 * 16];   // G[pair*16 + feat*2 + half]
    __shared__ int c4r_sh[NW];

    const int b = blockIdx.x;
    const int lane = threadIdx.x;

    Feat ft = wall_features(params_true + (size_t)b * NW * 6 + lane * 6);
    Feat fp = wall_features(params_pred + (size_t)b * NW * 6 + lane * 6);

    // Stage row features pair-interleaved: pair ip = lane>>1, half = lane&1.
    {
        float* g = G + (lane >> 1) * 16 + (lane & 1);
        g[0]  = ft.cx;   g[2]  = ft.cy;
        g[4]  = ft.area; g[6]  = ft.sr;
        g[8]  = ft.ar;   g[10] = ft.bx;
        g[12] = ft.by;   g[14] = ft.prob;
    }
    uint64_t nx2, ny2, na2, ns2, nr2, nbx2, nby2, np2, ten2;
    PK2(nx2,  -fp.cx,   -fp.cx);
    PK2(ny2,  -fp.cy,   -fp.cy);
    PK2(na2,  -fp.area, -fp.area);
    PK2(ns2,  -fp.sr,   -fp.sr);
    PK2(nr2,  -fp.ar,   -fp.ar);
    PK2(nbx2, -fp.bx,   -fp.bx);
    PK2(nby2, -fp.by,   -fp.by);
    PK2(np2,  -fp.prob, -fp.prob);
    PK2(ten2, 10.0f, 10.0f);
    __syncwarp();

    // Fill C two rows at a time (packed f32x2); track column min on the fly.
    float cm = INFV;
    int am = 0;
#pragma unroll 4
    for (int ip = 0; ip < 16; ip++) {
        const uint64_t* g = (const uint64_t*)(G + ip * 16);
        uint64_t x2 = g[0], y2 = g[1], a2 = g[2], s2 = g[3];
        uint64_t r2 = g[4], bx2 = g[5], by2 = g[6], p2 = g[7];

        uint64_t d0, d1, d2, d3, d4, d5, d6, dp, pd, t, cost2;
        ADD2(d0, x2,  nx2);
        ADD2(d1, y2,  ny2);
        ADD2(d2, a2,  na2);
        ADD2(d3, s2,  ns2);
        ADD2(d4, r2,  nr2);
        ADD2(d5, bx2, nbx2);
        ADD2(d6, by2, nby2);
        ADD2(dp, p2,  np2);
        MUL2(pd, d0, d0);
        FMA2(pd, d1, d1, pd);
        FMA2(pd, d2, d2, pd);
        FMA2(pd, d3, d3, pd);
        FMA2(pd, d4, d4, pd);
        FMA2(pd, d5, d5, pd);
        FMA2(pd, d6, d6, pd);
        MUL2(t, dp, dp);
        MUL2(t, t, ten2);
        FMA2(cost2, pd, p2, t);      // 10*dp^2 + param_d * iprob

        float c0, c1;
        UPK2(c0, c1, cost2);
        C[(2 * ip) * NW + lane] = c0;
        C[(2 * ip + 1) * NW + lane] = c1;
        if (c0 < cm) { cm = c0; am = 2 * ip; }
        if (c1 < cm) { cm = c1; am = 2 * ip + 1; }
    }
    __syncwarp();

    // ---- Phase 1: column reduction. v[j]=colmin, greedily match argmin rows.
    float v = cm, u = 0.0f;
    unsigned grp = __match_any_sync(FM, am);
    bool winner = ((__ffs(grp) - 1) == lane);
    int row4col = winner ? am : -1;
    c4r_sh[lane] = -1;
    __syncwarp();
    if (winner) c4r_sh[am] = lane;
    __syncwarp();
    int col4row = c4r_sh[lane];
    unsigned freerows = __ballot_sync(FM, col4row < 0);

    // ---- Phase 2': kick-free free-row pass with free-preferred ties.
    // key = (d:26 | matched:1 | lane:5); if the winning key's matched bit is
    // clear, the argmin column is free -> match. No row4col shfl needed.
    unsigned matchbit = (row4col >= 0) ? 32u : 0u;
    unsigned rem = freerows;
    while (rem) {
        const int i = __ffs(rem) - 1;
        rem &= rem - 1;
        float d = C[i * NW + lane] - v;   // >= 0 exactly (v = colmin)
        unsigned k = (__float_as_uint(d) & KMASK6) | matchbit | (unsigned)lane;
        unsigned m = __reduce_min_sync(FM, k);
        float umin = __uint_as_float(m & KMASK6);
        if (lane == i) u = umin;
        if (!(m & 32u)) {                 // free column won -> match
            int j = m & 31;
            if (lane == j) { row4col = i; matchbit = 32u; }
            if (lane == i) col4row = j;
            freerows &= ~(1u << i);
        }
    }

    // ---- Phase 3: SAP, biased slacks (slackb = slack + 1 > 0).
    if (freerows) {
        // Branchless M staging: M[j][l] = C[row4col[j]][l]; free columns get
        // a dummy row (never read before overwrite during augmentation).
        c4r_sh[lane] = row4col;
        __syncwarp();
#pragma unroll 1
        for (int j = 0; j < NW; j++) {
            int r = c4r_sh[j];
            M[j * NW + lane] = C[(r & 31) * NW + lane];
        }
        __syncwarp();
    }

    while (freerows) {
        const int i0 = __ffs(freerows) - 1;
        freerows &= freerows - 1;

        float ur = __shfl_sync(FM, u, row4col & 31);  // u[row4col[lane]]
        float ui = __shfl_sync(FM, u, i0);
        unsigned mkey = 0xFFFFFFFFu;
        // laneor = lane | matched-flag; ~0 once selected (SC member).
        unsigned laneor = (unsigned)lane | ((row4col >= 0) ? 32u : 0u);
        float spcb = INFV;                  // set once, at selection
        int pathcol = 32;                   // predecessor column (32 == i0)
        int j = 32;                         // previous selection (sentinel)
        float minValb = 1.0f;
        float slackb = (C[i0 * NW + lane] - ui - v) + 1.0f;   // >= 1
        int sink;

        for (;;) {
            unsigned skey = (__float_as_uint(slackb) & KMASK6) | laneor;
            bool upd = skey < mkey;
            mkey = upd ? skey : mkey;
            pathcol = upd ? j : pathcol;
            unsigned om = __reduce_min_sync(FM, mkey);
            j = om & 31;
            minValb = __uint_as_float(om & KMASK6);
            if (lane == j) {                // selection: freeze spcb, retire key
                spcb = minValb;
                laneor = 0xFFFFFFFFu;
                mkey = 0xFFFFFFFFu;
            }
            if (!(om & 32u)) { sink = j; break; }   // free column selected
            float urj = __shfl_sync(FM, ur, j);     // overlaps the M LDS
            slackb = M[j * NW + lane] - ((urj - minValb) + v);
        }

        // Dual updates. SC = selected lanes; scanned rows = {i0} U matched(SC).
        unsigned SC = __ballot_sync(FM, laneor == 0xFFFFFFFFu);
        float spcb_c4r = __shfl_sync(FM, spcb, col4row & 31);
        bool inSR = (lane == i0) ||
                    ((col4row >= 0) && ((SC >> col4row) & 1u));
        if (inSR)
            u += (lane == i0) ? (minValb - 1.0f) : (minValb - spcb_c4r);
        if ((SC >> lane) & 1u) v -= minValb - spcb;

        // Augment along the predecessor-column chain; refresh M on the way.
        int jj = sink;
        for (;;) {
            int pc = __shfl_sync(FM, pathcol, jj);
            int rc = __shfl_sync(FM, row4col, pc & 31);   // old row of pc
            int pi = (pc == 32) ? i0 : rc;
            if (lane == jj) row4col = pi;
            if (lane == pi) col4row = jj;
            M[jj * NW + lane] = C[pi * NW + lane];
            if (pc == 32) break;
            jj = pc;
        }
    }

    // loss = sum_i C[i][col4row[i]]
    float c = C[lane * NW + (col4row & 31)];
#pragma unroll
    for (int off = 16; off > 0; off >>= 1)
        c += __shfl_xor_sync(FM, c, off);
    if (lane == 0) out[b] = c;
}

extern "C" void kernel_launch(void* const* d_in, const int* in_sizes, int n_in,
                              void* d_out, int out_size) {
    const float* params_true = (const float*)d_in[0];
    const float* params_pred = (const float*)d_in[1];
    float* out = (float*)d_out;
    (void)in_sizes; (void)n_in; (void)out_size;
    floorplanet_kernel<<<2048, 32>>>(params_true, params_pred, out);
}